// round 1
// baseline (speedup 1.0000x reference)
#include <cuda_runtime.h>
#include <cuda_bf16.h>
#include <math.h>

#define NN 50000
#define EE 1600000
#define FIN 128
#define HID 256
#define NC 40

// ---------------- scratch (device globals; no allocation) ----------------
__device__ float g_deg[NN];
__device__ float g_inv[NN];
__device__ int   g_cnt[NN];
__device__ int   g_rowstart[NN + 1];
__device__ int   g_cursor[NN];
__device__ int   g_eidx[EE];
__device__ float g_ecoef[EE];
__device__ float g_aggx[(size_t)NN * FIN];
__device__ float g_h[(size_t)NN * HID];
__device__ float g_a[(size_t)NN * HID];

// ---------------- graph preprocessing ----------------
__global__ void init_kernel(float* deg, int* cnt) {
    int i = blockIdx.x * blockDim.x + threadIdx.x;
    if (i < NN) { deg[i] = 1.0f; cnt[i] = 0; }   // self-loop in degree
}

__global__ void count_kernel(const int* __restrict__ dst, float* deg, int* cnt) {
    int e = blockIdx.x * blockDim.x + threadIdx.x;
    if (e < EE) {
        int d = dst[e];
        atomicAdd(&deg[d], 1.0f);
        atomicAdd(&cnt[d], 1);
    }
}

__global__ void inv_kernel(const float* __restrict__ deg, float* inv) {
    int i = blockIdx.x * blockDim.x + threadIdx.x;
    if (i < NN) inv[i] = rsqrtf(deg[i]);
}

// single-block exclusive scan over g_cnt -> rowstart, cursor
__global__ void scan_kernel(const int* __restrict__ cnt, int* rowstart, int* cursor) {
    __shared__ int warp_sums[32];
    __shared__ int s_running;
    int tid = threadIdx.x, lane = tid & 31, w = tid >> 5;
    if (tid == 0) s_running = 0;
    __syncthreads();
    for (int base = 0; base < NN; base += 1024) {
        int i = base + tid;
        int v = (i < NN) ? cnt[i] : 0;
        int x = v;
        #pragma unroll
        for (int o = 1; o < 32; o <<= 1) {
            int t = __shfl_up_sync(0xFFFFFFFFu, x, o);
            if (lane >= o) x += t;
        }
        if (lane == 31) warp_sums[w] = x;
        __syncthreads();
        if (w == 0) {
            int s = warp_sums[lane];
            #pragma unroll
            for (int o = 1; o < 32; o <<= 1) {
                int t = __shfl_up_sync(0xFFFFFFFFu, s, o);
                if (lane >= o) s += t;
            }
            warp_sums[lane] = s;
        }
        __syncthreads();
        int inc = x + (w > 0 ? warp_sums[w - 1] : 0);
        int excl = s_running + inc - v;
        if (i < NN) { rowstart[i] = excl; cursor[i] = excl; }
        __syncthreads();
        if (tid == 1023) s_running += inc;   // inc of last thread == block total
        __syncthreads();
    }
    if (tid == 0) rowstart[NN] = s_running;
}

__global__ void fill_kernel(const int* __restrict__ src, const int* __restrict__ dst,
                            const float* __restrict__ inv,
                            int* cursor, int* eidx, float* ecoef) {
    int e = blockIdx.x * blockDim.x + threadIdx.x;
    if (e < EE) {
        int s = src[e], d = dst[e];
        int p = atomicAdd(&cursor[d], 1);
        eidx[p] = s;
        ecoef[p] = inv[s] * inv[d];
    }
}

// ---------------- SpMM aggregation: one warp per node, register accum ----------------
template <int F, int RELU, int BIAS>
__global__ void agg_kernel(const float* __restrict__ hin, float* __restrict__ out,
                           const int* __restrict__ rowstart,
                           const int* __restrict__ eidx, const float* __restrict__ ecoef,
                           const float* __restrict__ inv, const float* __restrict__ bias) {
    int node = (blockIdx.x * blockDim.x + threadIdx.x) >> 5;
    int lane = threadIdx.x & 31;
    if (node >= NN) return;
    const int KC = (F + 31) / 32;
    float acc[KC];
    float sn = inv[node];
    sn = sn * sn;
    const float* hrow = hin + (size_t)node * F;
    #pragma unroll
    for (int k = 0; k < KC; k++) {
        int c = lane + 32 * k;
        acc[k] = (c < F) ? hrow[c] * sn : 0.0f;
    }
    int beg = rowstart[node], end = rowstart[node + 1];
    for (int j = beg; j < end; j++) {
        int s = __ldg(eidx + j);
        float cf = __ldg(ecoef + j);
        const float* hs = hin + (size_t)s * F;
        #pragma unroll
        for (int k = 0; k < KC; k++) {
            int c = lane + 32 * k;
            if (c < F) acc[k] = fmaf(cf, __ldg(hs + c), acc[k]);
        }
    }
    float* orow = out + (size_t)node * F;
    #pragma unroll
    for (int k = 0; k < KC; k++) {
        int c = lane + 32 * k;
        if (c < F) {
            float v = acc[k] + (BIAS ? bias[c] : 0.0f);
            if (RELU) v = fmaxf(v, 0.0f);
            orow[c] = v;
        }
    }
}

// ---------------- tiled fp32 GEMM: C[M,Nn] = A[M,K] @ W[K,Nn] (+bias)(+relu) ----------------
// BM=128, BN=64, BK=16, 256 threads, 8x4 micro-tile per thread
__global__ void gemm_kernel(const float* __restrict__ A, const float* __restrict__ W,
                            const float* __restrict__ bias, float* __restrict__ C,
                            int K, int Nn, int relu) {
    __shared__ __align__(16) float As[16][132];
    __shared__ __align__(16) float Bs[16][68];
    int tid = threadIdx.x;
    int m0 = blockIdx.y * 128;
    int n0 = blockIdx.x * 64;
    int tx = tid & 15;    // n-group (4 cols)
    int ty = tid >> 4;    // m-group (8 rows)
    float acc[8][4];
    #pragma unroll
    for (int i = 0; i < 8; i++)
        #pragma unroll
        for (int j = 0; j < 4; j++) acc[i][j] = 0.0f;

    for (int k0 = 0; k0 < K; k0 += 16) {
        // A tile: 128x16 = 512 float4, 2 per thread
        #pragma unroll
        for (int t = 0; t < 2; t++) {
            int idx = tid + t * 256;
            int r = idx >> 2;
            int c4 = idx & 3;
            float4 v = make_float4(0.f, 0.f, 0.f, 0.f);
            int gr = m0 + r;
            if (gr < NN) v = *(const float4*)(A + (size_t)gr * K + k0 + c4 * 4);
            As[c4 * 4 + 0][r] = v.x;
            As[c4 * 4 + 1][r] = v.y;
            As[c4 * 4 + 2][r] = v.z;
            As[c4 * 4 + 3][r] = v.w;
        }
        // W tile: 16x64 = 256 float4, 1 per thread
        {
            int r = tid >> 4;       // k row 0..15
            int c4 = tid & 15;      // n quad
            int gn = n0 + c4 * 4;
            float4 v = make_float4(0.f, 0.f, 0.f, 0.f);
            if (gn < Nn) v = *(const float4*)(W + (size_t)(k0 + r) * Nn + gn);
            *(float4*)&Bs[r][c4 * 4] = v;
        }
        __syncthreads();
        #pragma unroll
        for (int kk = 0; kk < 16; kk++) {
            float4 a0 = *(const float4*)&As[kk][ty * 8];
            float4 a1 = *(const float4*)&As[kk][ty * 8 + 4];
            float4 b0 = *(const float4*)&Bs[kk][tx * 4];
            float a[8] = {a0.x, a0.y, a0.z, a0.w, a1.x, a1.y, a1.z, a1.w};
            float b[4] = {b0.x, b0.y, b0.z, b0.w};
            #pragma unroll
            for (int i = 0; i < 8; i++)
                #pragma unroll
                for (int j = 0; j < 4; j++)
                    acc[i][j] = fmaf(a[i], b[j], acc[i][j]);
        }
        __syncthreads();
    }
    #pragma unroll
    for (int i = 0; i < 8; i++) {
        int gm = m0 + ty * 8 + i;
        if (gm >= NN) continue;
        #pragma unroll
        for (int j = 0; j < 4; j++) {
            int gn = n0 + tx * 4 + j;
            if (gn < Nn) {
                float v = acc[i][j] + (bias ? bias[gn] : 0.0f);
                if (relu) v = fmaxf(v, 0.0f);
                C[(size_t)gm * Nn + gn] = v;
            }
        }
    }
}

// ---------------- log_softmax over 40 cols, one warp per row ----------------
__global__ void lsm_kernel(const float* __restrict__ z, float* __restrict__ out) {
    int row = (blockIdx.x * blockDim.x + threadIdx.x) >> 5;
    int lane = threadIdx.x & 31;
    if (row >= NN) return;
    const float* zr = z + (size_t)row * NC;
    float v0 = (lane < NC) ? zr[lane] : -1e30f;
    float v1 = (lane + 32 < NC) ? zr[lane + 32] : -1e30f;
    float m = fmaxf(v0, v1);
    #pragma unroll
    for (int o = 16; o > 0; o >>= 1) m = fmaxf(m, __shfl_xor_sync(0xFFFFFFFFu, m, o));
    float s = ((lane < NC) ? expf(v0 - m) : 0.0f) + ((lane + 32 < NC) ? expf(v1 - m) : 0.0f);
    #pragma unroll
    for (int o = 16; o > 0; o >>= 1) s += __shfl_xor_sync(0xFFFFFFFFu, s, o);
    float lse = m + logf(s);
    float* orow = out + (size_t)row * NC;
    if (lane < NC) orow[lane] = v0 - lse;
    if (lane + 32 < NC) orow[lane + 32] = v1 - lse;
}

// ---------------- host launch ----------------
extern "C" void kernel_launch(void* const* d_in, const int* in_sizes, int n_in,
                              void* d_out, int out_size) {
    const float* x  = (const float*)d_in[0];
    const int*   ei = (const int*)d_in[1];
    const float* W1 = (const float*)d_in[2];
    const float* b1 = (const float*)d_in[3];
    const float* W2 = (const float*)d_in[4];
    const float* b2 = (const float*)d_in[5];
    const float* W3 = (const float*)d_in[6];
    const float* b3 = (const float*)d_in[7];
    const float* W4 = (const float*)d_in[8];
    const float* b4 = (const float*)d_in[9];
    float* out = (float*)d_out;

    const int* src = ei;
    const int* dst = ei + EE;

    float *deg, *inv, *ecoef, *aggx, *h, *a;
    int *cnt, *rowstart, *cursor, *eidx;
    cudaGetSymbolAddress((void**)&deg, g_deg);
    cudaGetSymbolAddress((void**)&inv, g_inv);
    cudaGetSymbolAddress((void**)&cnt, g_cnt);
    cudaGetSymbolAddress((void**)&rowstart, g_rowstart);
    cudaGetSymbolAddress((void**)&cursor, g_cursor);
    cudaGetSymbolAddress((void**)&eidx, g_eidx);
    cudaGetSymbolAddress((void**)&ecoef, g_ecoef);
    cudaGetSymbolAddress((void**)&aggx, g_aggx);
    cudaGetSymbolAddress((void**)&h, g_h);
    cudaGetSymbolAddress((void**)&a, g_a);

    const int TPB = 256;
    int gN = (NN + TPB - 1) / TPB;
    int gE = (EE + TPB - 1) / TPB;
    int gWarpN = (NN * 32 + TPB - 1) / TPB;

    // graph preprocessing (CSR by dst)
    init_kernel<<<gN, TPB>>>(deg, cnt);
    count_kernel<<<gE, TPB>>>(dst, deg, cnt);
    inv_kernel<<<gN, TPB>>>(deg, inv);
    scan_kernel<<<1, 1024>>>(cnt, rowstart, cursor);
    fill_kernel<<<gE, TPB>>>(src, dst, inv, cursor, eidx, ecoef);

    dim3 gemmGridHID((HID + 63) / 64, (NN + 127) / 128);
    dim3 gemmGridC((NC + 63) / 64, (NN + 127) / 128);

    // Layer 1: aggregate X at F=128 first (cheaper), then GEMM+bias+relu
    agg_kernel<FIN, 0, 0><<<gWarpN, TPB>>>(x, aggx, rowstart, eidx, ecoef, inv, nullptr);
    gemm_kernel<<<gemmGridHID, TPB>>>(aggx, W1, b1, a, FIN, HID, 1);

    // Layer 2: GEMM then aggregate+bias+relu
    gemm_kernel<<<gemmGridHID, TPB>>>(a, W2, nullptr, h, HID, HID, 0);
    agg_kernel<HID, 1, 1><<<gWarpN, TPB>>>(h, a, rowstart, eidx, ecoef, inv, b2);

    // Layer 3
    gemm_kernel<<<gemmGridHID, TPB>>>(a, W3, nullptr, h, HID, HID, 0);
    agg_kernel<HID, 1, 1><<<gWarpN, TPB>>>(h, a, rowstart, eidx, ecoef, inv, b3);

    // Layer 4: GEMM to 40, aggregate at F=40 (+bias), then log_softmax
    gemm_kernel<<<gemmGridC, TPB>>>(a, W4, nullptr, h, HID, NC, 0);
    agg_kernel<NC, 0, 1><<<gWarpN, TPB>>>(h, a, rowstart, eidx, ecoef, inv, b4);
    lsm_kernel<<<gWarpN, TPB>>>(a, out);
}